// round 1
// baseline (speedup 1.0000x reference)
#include <cuda_runtime.h>
#include <cuda_bf16.h>

#define BATCH 65536
#define XDIM  362
#define GS    19
#define BM    64
#define BP    (BATCH + BM)   // padded rows for tile overhang

typedef unsigned long long u64;

// ---------------- scratch (device globals; no allocation) ----------------
__device__ float g_att[BATCH * 6];
__device__ int   g_ptr[BATCH];
__device__ int   g_cnt[3];
__device__ int   g_off[4];
__device__ int   g_cur[3];
__device__ int   g_rowlist[BP];
__device__ float g_h2T[400ull * BP];   // h2 stored transposed: [c][pos]

// ---------------- f32x2 helpers ----------------
__device__ __forceinline__ u64 pack2(float w) {
    u64 r; asm("mov.b64 %0, {%1,%1};" : "=l"(r) : "f"(w)); return r;
}
__device__ __forceinline__ void fma2(u64 &acc, u64 a, u64 b) {
    asm("fma.rn.f32x2 %0, %1, %2, %0;" : "+l"(acc) : "l"(a), "l"(b));
}
__device__ __forceinline__ float2 unpack2(u64 v) {
    float2 f; asm("mov.b64 {%0,%1}, %2;" : "=f"(f.x), "=f"(f.y) : "l"(v)); return f;
}
__device__ __forceinline__ int clampi(int v) { return min(max(v, 1), XDIM - 1); }

// tile -> (action, base position, valid rows)
__device__ __forceinline__ bool find_tile(int t, int &a, int &pos0, int &nrows) {
    #pragma unroll
    for (int q = 0; q < 3; q++) {
        int cnt = g_cnt[q];
        int ta  = (cnt + BM - 1) >> 6;
        if (t < ta) { a = q; pos0 = g_off[q] + t * BM; nrows = min(BM, cnt - t * BM); return true; }
        t -= ta;
    }
    return false;
}

// ---------------- kernel 0: zero counters ----------------
__global__ void zero_k() {
    int t = threadIdx.x;
    if (t < 3) { g_cnt[t] = 0; g_cur[t] = 0; }
}

// ---------------- kernel 1: copy + argmax + gather + count ----------------
__global__ __launch_bounds__(256) void prep_k(const float* __restrict__ x,
                                              const int* __restrict__ act,
                                              float* __restrict__ out) {
    int warp = (blockIdx.x * blockDim.x + threadIdx.x) >> 5;
    int lane = threadIdx.x & 31;
    if (warp >= BATCH) return;

    const float2* xr = (const float2*)(x + (size_t)warp * XDIM);
    float2*       orr = (float2*)(out + (size_t)warp * XDIM);

    float best = -3.4e38f; int bidx = 0;
    #pragma unroll 2
    for (int j = lane; j < XDIM / 2; j += 32) {
        float2 v = xr[j];
        orr[j] = v;
        if (v.x > best) { best = v.x; bidx = 2 * j; }
        if (v.y > best) { best = v.y; bidx = 2 * j + 1; }
    }
    // warp argmax reduction, first-index wins on ties
    #pragma unroll
    for (int off = 16; off; off >>= 1) {
        float ov = __shfl_down_sync(0xffffffffu, best, off);
        int   oi = __shfl_down_sync(0xffffffffu, bidx, off);
        if (ov > best || (ov == best && oi < bidx)) { best = ov; bidx = oi; }
    }
    int ptr = __shfl_sync(0xffffffffu, bidx, 0);

    if (lane == 0) {
        g_ptr[warp] = ptr;
        atomicAdd(&g_cnt[act[warp]], 1);
    }
    if (lane < 6) {
        int id = 0;
        if      (lane == 1) id = ptr;
        else if (lane == 2) id = clampi(ptr - GS);
        else if (lane == 3) id = clampi(ptr + GS);
        else if (lane == 4) id = clampi(ptr - 1);
        else if (lane == 5) id = clampi(ptr + 1);
        g_att[warp * 6 + lane] = x[(size_t)warp * XDIM + id];
    }
}

// ---------------- kernel 2: offsets ----------------
__global__ void scan_k() {
    g_off[0] = 0;
    g_off[1] = g_cnt[0];
    g_off[2] = g_cnt[0] + g_cnt[1];
    g_off[3] = g_cnt[0] + g_cnt[1] + g_cnt[2];
}

// ---------------- kernel 3: compact rows by action ----------------
__global__ void compact_k(const int* __restrict__ act) {
    int r = blockIdx.x * blockDim.x + threadIdx.x;
    if (r < BATCH) {
        int a = act[r];
        int p = g_off[a] + atomicAdd(&g_cur[a], 1);
        g_rowlist[p] = r;
    }
}

// ---------------- kernel 4: L1 (6->100) + L2 (100->400) ----------------
__global__ __launch_bounds__(256) void kA(const float* __restrict__ W1,
                                          const float* __restrict__ b1,
                                          const float* __restrict__ W2,
                                          const float* __restrict__ b2) {
    __shared__ __align__(16) float att_s[BM * 6];
    __shared__ __align__(16) float W1s[600];
    __shared__ __align__(16) float b1s[100];
    __shared__ __align__(16) float b2s[400];
    __shared__ __align__(16) float h1T[100 * BM];    // [k][row]
    __shared__ __align__(16) float W2s[25 * 128];    // stage; reused as bounce [32][65]

    int a, pos0, nrows;
    if (!find_tile(blockIdx.x, a, pos0, nrows)) return;
    int tid = threadIdx.x;

    for (int e = tid; e < BM * 6; e += 256) {
        int i = e / 6;
        att_s[e] = (i < nrows) ? g_att[g_rowlist[pos0 + i] * 6 + (e % 6)] : 0.f;
    }
    for (int e = tid; e < 600; e += 256) W1s[e] = W1[a * 600 + e];
    for (int e = tid; e < 100; e += 256) b1s[e] = b1[a * 100 + e];
    for (int e = tid; e < 400; e += 256) b2s[e] = b2[a * 400 + e];
    __syncthreads();

    // L1: h1T[n][i] = relu(att[i] . W1[:,n] + b1[n])
    for (int e = tid; e < 100 * BM; e += 256) {
        int n = e >> 6, i = e & 63;
        float acc = b1s[n];
        #pragma unroll
        for (int k = 0; k < 6; k++) acc += att_s[i * 6 + k] * W1s[k * 100 + n];
        h1T[n * BM + i] = fmaxf(acc, 0.f);
    }

    int ty = tid >> 5, tx = tid & 31;
    int r0 = ty * 8;
    const float* W2a = W2 + a * 40000;

    for (int pass = 0; pass < 4; pass++) {
        int c0 = pass * 128;
        u64 acc[4][4];
        #pragma unroll
        for (int p = 0; p < 4; p++)
            #pragma unroll
            for (int j = 0; j < 4; j++) acc[p][j] = 0ull;

        for (int kc = 0; kc < 100; kc += 25) {
            __syncthreads();
            for (int e = tid; e < 25 * 128; e += 256) {
                int kl = e >> 7, n = e & 127;
                int c = c0 + n;
                W2s[e] = (c < 400) ? W2a[(kc + kl) * 400 + c] : 0.f;
            }
            __syncthreads();
            #pragma unroll
            for (int kl = 0; kl < 25; kl++) {
                int k = kc + kl;
                u64 a0 = *(const u64*)&h1T[k * BM + r0];
                u64 a1 = *(const u64*)&h1T[k * BM + r0 + 2];
                u64 a2 = *(const u64*)&h1T[k * BM + r0 + 4];
                u64 a3 = *(const u64*)&h1T[k * BM + r0 + 6];
                #pragma unroll
                for (int j = 0; j < 4; j++) {
                    u64 w2 = pack2(W2s[kl * 128 + j * 32 + tx]);
                    fma2(acc[0][j], a0, w2);
                    fma2(acc[1][j], a1, w2);
                    fma2(acc[2][j], a2, w2);
                    fma2(acc[3][j], a3, w2);
                }
            }
        }
        // bias+relu, write transposed h2 via smem bounce for coalesced STG
        float* bounce = W2s;  // [32][65]
        #pragma unroll 1
        for (int j = 0; j < 4; j++) {
            int c = c0 + j * 32 + tx;
            __syncthreads();
            float bias = (c < 400) ? b2s[c] : 0.f;
            #pragma unroll
            for (int p = 0; p < 4; p++) {
                float2 v = unpack2(acc[p][j]);
                bounce[tx * 65 + r0 + 2 * p]     = fmaxf(v.x + bias, 0.f);
                bounce[tx * 65 + r0 + 2 * p + 1] = fmaxf(v.y + bias, 0.f);
            }
            __syncthreads();
            for (int e = tid; e < 32 * BM; e += 256) {
                int cl = e >> 6, r = e & 63;
                int cg = c0 + j * 32 + cl;
                if (cg < 400 && r < nrows)
                    g_h2T[(size_t)cg * BP + pos0 + r] = bounce[cl * 65 + r];
            }
        }
    }
}

// ---------------- kernel 5: L3 (400->100) + L4 (100->6) + scatter ----------------
__global__ __launch_bounds__(256) void kB(const float* __restrict__ W3,
                                          const float* __restrict__ b3,
                                          const float* __restrict__ W4,
                                          const float* __restrict__ b4,
                                          float* __restrict__ out) {
    __shared__ __align__(16) float A_sT[16 * BM];     // [kl][row]
    __shared__ __align__(16) float W3s[16 * 128];
    __shared__ __align__(16) float h3T[100 * 65];     // [n][row], padded stride 65
    __shared__ __align__(16) float W4s[600];
    __shared__ __align__(16) float b3s[100];
    __shared__ __align__(16) float b4s[8];
    __shared__ __align__(16) float pred_s[BM * 6];

    int a, pos0, nrows;
    if (!find_tile(blockIdx.x, a, pos0, nrows)) return;
    int tid = threadIdx.x;

    for (int e = tid; e < 600; e += 256) W4s[e] = W4[a * 600 + e];
    for (int e = tid; e < 100; e += 256) b3s[e] = b3[a * 100 + e];
    if (tid < 6) b4s[tid] = b4[a * 6 + tid];

    int ty = tid >> 5, tx = tid & 31;
    int r0 = ty * 8;
    const float* W3a = W3 + a * 40000;

    u64 acc[4][4];
    #pragma unroll
    for (int p = 0; p < 4; p++)
        #pragma unroll
        for (int j = 0; j < 4; j++) acc[p][j] = 0ull;

    for (int kc = 0; kc < 400; kc += 16) {
        __syncthreads();
        for (int e = tid; e < 16 * BM; e += 256) {
            int kl = e >> 6, r = e & 63;
            A_sT[e] = g_h2T[(size_t)(kc + kl) * BP + pos0 + r];
        }
        for (int e = tid; e < 16 * 128; e += 256) {
            int kl = e >> 7, n = e & 127;
            W3s[e] = (n < 100) ? W3a[(kc + kl) * 100 + n] : 0.f;
        }
        __syncthreads();
        #pragma unroll
        for (int kl = 0; kl < 16; kl++) {
            u64 a0 = *(const u64*)&A_sT[kl * BM + r0];
            u64 a1 = *(const u64*)&A_sT[kl * BM + r0 + 2];
            u64 a2 = *(const u64*)&A_sT[kl * BM + r0 + 4];
            u64 a3 = *(const u64*)&A_sT[kl * BM + r0 + 6];
            #pragma unroll
            for (int j = 0; j < 4; j++) {
                u64 w2 = pack2(W3s[kl * 128 + j * 32 + tx]);
                fma2(acc[0][j], a0, w2);
                fma2(acc[1][j], a1, w2);
                fma2(acc[2][j], a2, w2);
                fma2(acc[3][j], a3, w2);
            }
        }
    }
    __syncthreads();
    // bias + relu -> h3T
    #pragma unroll
    for (int j = 0; j < 4; j++) {
        int n = j * 32 + tx;
        if (n < 100) {
            float bias = b3s[n];
            #pragma unroll
            for (int p = 0; p < 4; p++) {
                float2 v = unpack2(acc[p][j]);
                h3T[n * 65 + r0 + 2 * p]     = fmaxf(v.x + bias, 0.f);
                h3T[n * 65 + r0 + 2 * p + 1] = fmaxf(v.y + bias, 0.f);
            }
        }
    }
    __syncthreads();
    // L4: pred[r][m] = h3[r] . W4[:,m] + b4[m]
    for (int e = tid; e < BM * 6; e += 256) {
        int r = e / 6, m = e % 6;
        float s = b4s[m];
        #pragma unroll 4
        for (int k = 0; k < 100; k++) s += h3T[k * 65 + r] * W4s[k * 6 + m];
        pred_s[r * 6 + m] = s;
    }
    __syncthreads();
    // scatter: ordered stores per row; last j wins on duplicate indices
    if (tid < nrows) {
        int row = g_rowlist[pos0 + tid];
        int ptr = g_ptr[row];
        float* orow = out + (size_t)row * XDIM;
        int idx[6];
        idx[0] = 0;
        idx[1] = ptr;
        idx[2] = clampi(ptr - GS);
        idx[3] = clampi(ptr + GS);
        idx[4] = clampi(ptr - 1);
        idx[5] = clampi(ptr + 1);
        #pragma unroll 1
        for (int j = 0; j < 6; j++)
            orow[idx[j]] = g_att[row * 6 + j] + pred_s[tid * 6 + j];
    }
}

// ---------------- launch ----------------
extern "C" void kernel_launch(void* const* d_in, const int* in_sizes, int n_in,
                              void* d_out, int out_size) {
    const float* x  = (const float*)d_in[0];
    const float* W1 = (const float*)d_in[1];
    const float* b1 = (const float*)d_in[2];
    const float* W2 = (const float*)d_in[3];
    const float* b2 = (const float*)d_in[4];
    const float* W3 = (const float*)d_in[5];
    const float* b3 = (const float*)d_in[6];
    const float* W4 = (const float*)d_in[7];
    const float* b4 = (const float*)d_in[8];
    const int*  act = (const int*)d_in[9];
    float* out = (float*)d_out;

    zero_k<<<1, 32>>>();
    prep_k<<<BATCH / 8, 256>>>(x, act, out);
    scan_k<<<1, 1>>>();
    compact_k<<<BATCH / 256, 256>>>(act);
    kA<<<BATCH / BM + 3, 256>>>(W1, b1, W2, b2);
    kB<<<BATCH / BM + 3, 256>>>(W3, b3, W4, b4, out);
}